// round 2
// baseline (speedup 1.0000x reference)
#include <cuda_runtime.h>

#define HW        (1024*2048)
#define NBLK      1024
#define BPIX      2048
#define SRC_PIX   (128*256)
#define MEMD      256
#define EGO_W     2048

// ---------------- scratch (device globals; allocation-free at runtime) -----
__device__ long long g_thr;
__device__ int       g_is64;    // proj_indices element size flag (1 = int64)
__device__ int       g_msize;   // mask element size in bytes: 1, 4, or 8
__device__ int       g_blkcnt[NBLK];
__device__ int       g_blkoff[NBLK + 1];
__device__ int       g_Pinc[HW];                 // inclusive inlier prefix count
__device__ float     g_G[SRC_PIX * MEMD];        // projected source features (+bias)

// ---------------- helpers ---------------------------------------------------
__device__ __forceinline__ int warp_incl_scan(int v) {
    int lane = threadIdx.x & 31;
#pragma unroll
    for (int o = 1; o < 32; o <<= 1) {
        int t = __shfl_up_sync(0xffffffffu, v, o);
        if (lane >= o) v += t;
    }
    return v;
}

// Load 8 consecutive mask pixels starting at pixel index `base` (multiple of 8),
// honoring the detected element size. Returns bits and their sum.
__device__ __forceinline__ int load8bits(const void* mask, size_t base, int msize,
                                         int bits[8]) {
    if (msize == 1) {
        uint2 v = *(const uint2*)((const unsigned char*)mask + base);
#pragma unroll
        for (int i = 0; i < 4; i++) bits[i]     = ((v.x >> (8 * i)) & 0xff) != 0;
#pragma unroll
        for (int i = 0; i < 4; i++) bits[4 + i] = ((v.y >> (8 * i)) & 0xff) != 0;
    } else if (msize == 4) {
        const uint4* p = (const uint4*)((const unsigned*)mask + base);
        uint4 a = p[0], b = p[1];
        bits[0] = a.x != 0; bits[1] = a.y != 0; bits[2] = a.z != 0; bits[3] = a.w != 0;
        bits[4] = b.x != 0; bits[5] = b.y != 0; bits[6] = b.z != 0; bits[7] = b.w != 0;
    } else {
        const uint4* p = (const uint4*)((const unsigned long long*)mask + base);
        uint4 a = p[0], b = p[1], c = p[2], d = p[3];
        bits[0] = (a.x | a.y) != 0; bits[1] = (a.z | a.w) != 0;
        bits[2] = (b.x | b.y) != 0; bits[3] = (b.z | b.w) != 0;
        bits[4] = (c.x | c.y) != 0; bits[5] = (c.z | c.w) != 0;
        bits[6] = (d.x | d.y) != 0; bits[7] = (d.z | d.w) != 0;
    }
    int s = 0;
#pragma unroll
    for (int i = 0; i < 8; i++) s += bits[i];
    return s;
}

// ---------------- K0: init + dtype detection (proj + mask) ------------------
__global__ void k_init(const int* __restrict__ p32, int n,
                       const unsigned* __restrict__ mw) {
    g_thr = 0x8000000000000000LL;  // LLONG_MIN

    // proj_indices: int64 (odd words all 0/-1) vs int32 (odd words random)
    int probes = n / 2 < 256 ? n / 2 : 256;
    int is64 = 1;
    for (int k = 0; k < probes; k++) {
        int hi = p32[2 * k + 1];
        if (hi != 0 && hi != -1) { is64 = 0; break; }
    }
    g_is64 = is64;

    // mask dtype: probe first 1024 32-bit words.
    // float32 0/1 data -> words in {0, 0x3F800000}
    // int32   0/1 data -> words in {0, 1}
    // int64   0/1 data -> even words in {0,1}, odd words 0
    // byte bool        -> words with multiple 0x01 bytes, none of the above
    bool allF = true, allI = true, oddZero = true;
    for (int k = 0; k < 1024; k++) {
        unsigned v = mw[k];
        if (v != 0u && v != 0x3F800000u) allF = false;
        if (v > 1u) allI = false;
        if ((k & 1) && v != 0u) oddZero = false;
    }
    int msize;
    if (allI)      msize = oddZero ? 8 : 4;
    else if (allF) msize = 4;
    else           msize = 1;
    g_msize = msize;
}

// ---------------- K1: max(proj_indices) -> g_thr -----------------------------
__global__ void k_max(const void* __restrict__ proj, int n) {
    int is64 = g_is64;
    long long m = 0x8000000000000000LL;
    int stride = gridDim.x * blockDim.x;
    for (int i = blockIdx.x * blockDim.x + threadIdx.x; i < n; i += stride) {
        long long v = is64 ? ((const long long*)proj)[i]
                           : (long long)((const int*)proj)[i];
        m = v > m ? v : m;
    }
#pragma unroll
    for (int o = 16; o; o >>= 1) {
        long long t = __shfl_down_sync(0xffffffffu, m, o);
        m = t > m ? t : m;
    }
    if ((threadIdx.x & 31) == 0) atomicMax(&g_thr, m);
}

// ---------------- K2: per-block inlier counts -------------------------------
__global__ void __launch_bounds__(256) k_count(const void* __restrict__ mask) {
    int t = threadIdx.x;
    int msize = g_msize;
    size_t base = (size_t)blockIdx.x * BPIX + (size_t)t * 8;
    int bits[8];
    int c = load8bits(mask, base, msize, bits);
#pragma unroll
    for (int o = 16; o; o >>= 1) c += __shfl_down_sync(0xffffffffu, c, o);
    __shared__ int ws[8];
    if ((t & 31) == 0) ws[t >> 5] = c;
    __syncthreads();
    if (t == 0) {
        int s = 0;
#pragma unroll
        for (int i = 0; i < 8; i++) s += ws[i];
        g_blkcnt[blockIdx.x] = s;
    }
}

// ---------------- K3: scan block counts (single block) ----------------------
__global__ void __launch_bounds__(1024) k_scan() {
    int t = threadIdx.x;
    int v = g_blkcnt[t];
    int incl = warp_incl_scan(v);
    __shared__ int ws[32];
    if ((t & 31) == 31) ws[t >> 5] = incl;
    __syncthreads();
    if (t < 32) ws[t] = warp_incl_scan(ws[t]);
    __syncthreads();
    if (t >= 32) incl += ws[(t >> 5) - 1];
    g_blkoff[t] = incl - v;               // exclusive offset
    if (t == 1023) g_blkoff[NBLK] = incl; // total inliers
}

// ---------------- K4: per-pixel inclusive prefix ----------------------------
__global__ void __launch_bounds__(256) k_prefix(const void* __restrict__ mask) {
    int t = threadIdx.x, b = blockIdx.x;
    int msize = g_msize;
    size_t base = (size_t)b * BPIX + (size_t)t * 8;
    int bits[8];
    int s = load8bits(mask, base, msize, bits);

    int incl = warp_incl_scan(s);
    __shared__ int ws[8];
    int w = t >> 5;
    if ((t & 31) == 31) ws[w] = incl;
    __syncthreads();
    if (t == 0) {
        int acc = 0;
#pragma unroll
        for (int i = 0; i < 8; i++) { int tmp = ws[i]; ws[i] = acc; acc += tmp; }
    }
    __syncthreads();
    int run = g_blkoff[b] + (incl - s) + ws[w];
    int outv[8];
#pragma unroll
    for (int i = 0; i < 8; i++) { run += bits[i]; outv[i] = run; }
    *(int4*)&g_Pinc[base]     = make_int4(outv[0], outv[1], outv[2], outv[3]);
    *(int4*)&g_Pinc[base + 4] = make_int4(outv[4], outv[5], outv[6], outv[7]);
}

// ---------------- K5: project source grid through W (+bias) -----------------
// G[p][n] = sum_c feat[c][p] * W[n][c] + b[n]    (p over 128x256 source pixels)
__global__ void __launch_bounds__(256) k_gemmG(const float* __restrict__ feat,
                                               const float* __restrict__ Wl,
                                               const float* __restrict__ bl) {
    __shared__ float As[64][128];   // [k][px]
    __shared__ float Ws[64][64];    // [n_local][k]
    int pxb = blockIdx.x * 128;
    int nb  = blockIdx.y * 64;
    int t = threadIdx.x;

    for (int i = t; i < 64 * 128; i += 256) {
        int k = i >> 7, px = i & 127;
        As[k][px] = feat[k * SRC_PIX + pxb + px];
    }
    for (int i = t; i < 64 * 16; i += 256) {
        int nl = i >> 4, k4 = i & 15;
        *(float4*)&Ws[nl][k4 * 4] = *(const float4*)&Wl[(nb + nl) * 64 + k4 * 4];
    }
    __syncthreads();

    int lane = t & 31, w = t >> 5;
    int px0 = lane * 4;
    int n0  = w * 8;
    float acc[4][8];
#pragma unroll
    for (int i = 0; i < 4; i++)
#pragma unroll
        for (int j = 0; j < 8; j++) acc[i][j] = 0.0f;

#pragma unroll 8
    for (int k = 0; k < 64; k++) {
        float4 a4 = *(float4*)&As[k][px0];
        float av[4] = {a4.x, a4.y, a4.z, a4.w};
#pragma unroll
        for (int j = 0; j < 8; j++) {
            float bb = Ws[n0 + j][k];
#pragma unroll
            for (int i = 0; i < 4; i++) acc[i][j] = fmaf(av[i], bb, acc[i][j]);
        }
    }

#pragma unroll
    for (int i = 0; i < 4; i++) {
        int row = pxb + px0 + i;
#pragma unroll
        for (int j = 0; j < 8; j++)
            g_G[row * MEMD + nb + n0 + j] = acc[i][j] + bl[nb + n0 + j];
    }
}

// ---------------- K6: main fused gather + interpolate + transpose -----------
__global__ void __launch_bounds__(256) k_main(const void* __restrict__ proj,
                                              float* __restrict__ out,
                                              float* __restrict__ maskout_f,
                                              unsigned char* __restrict__ maskout_b,
                                              int n) {
    __shared__ int   sI[4][32];
    __shared__ float sWt[4][32];
    __shared__ float sOut[256 * 33];

    int tid = threadIdx.x;
    int rbase = blockIdx.x * 32;

    if (tid < 32) {
        int r = rbase + tid;
        int i0 = 0, i1 = 0, i2 = 0, i3 = 0;
        float w0 = 0.f, w1 = 0.f, w2 = 0.f, w3 = 0.f;
        if (r < n) {
            long long pj = g_is64 ? ((const long long*)proj)[r]
                                  : (long long)((const int*)proj)[r];
            bool m = pj < g_thr;
            if (maskout_f) maskout_f[r] = m ? 1.0f : 0.0f;
            if (maskout_b) maskout_b[r] = m ? 1 : 0;
            if (m) {
                long long jc = pj < 0 ? 0 : (pj > (long long)(HW - 1) ? (long long)(HW - 1) : pj);
                int j = (int)jc;
                int nin = g_blkoff[NBLK];
                int p;
                if (j < nin) {           // j-th inlier pixel
                    int tgt = j + 1, lo = 0, hi = HW - 1;
                    while (lo < hi) {
                        int mid = (lo + hi) >> 1;
                        if (__ldg(&g_Pinc[mid]) >= tgt) hi = mid; else lo = mid + 1;
                    }
                    p = lo;
                } else {                 // (j - nin)-th outlier pixel
                    int tgt = j - nin + 1, lo = 0, hi = HW - 1;
                    while (lo < hi) {
                        int mid = (lo + hi) >> 1;
                        if (mid + 1 - __ldg(&g_Pinc[mid]) >= tgt) hi = mid; else lo = mid + 1;
                    }
                    p = lo;
                }
                int y = p >> 11, x = p & (EGO_W - 1);
                float sy = y * (127.0f / 1023.0f);
                float sx = x * (255.0f / 2047.0f);
                int y0 = (int)sy; if (y0 > 127) y0 = 127;
                int x0 = (int)sx; if (x0 > 255) x0 = 255;
                int y1 = y0 + 1 > 127 ? 127 : y0 + 1;
                int x1 = x0 + 1 > 255 ? 255 : x0 + 1;
                float wy = sy - (float)y0, wx = sx - (float)x0;
                w0 = (1.f - wy) * (1.f - wx);
                w1 = (1.f - wy) * wx;
                w2 = wy * (1.f - wx);
                w3 = wy * wx;
                i0 = y0 * 256 + x0; i1 = y0 * 256 + x1;
                i2 = y1 * 256 + x0; i3 = y1 * 256 + x1;
            }
        }
        sI[0][tid] = i0; sI[1][tid] = i1; sI[2][tid] = i2; sI[3][tid] = i3;
        sWt[0][tid] = w0; sWt[1][tid] = w1; sWt[2][tid] = w2; sWt[3][tid] = w3;
    }
    __syncthreads();

    int w = tid >> 5, lane = tid & 31;
#pragma unroll
    for (int rr = 0; rr < 4; rr++) {
        int rl = (w << 2) + rr;
        const float* g0 = g_G + sI[0][rl] * MEMD;
        const float* g1 = g_G + sI[1][rl] * MEMD;
        const float* g2 = g_G + sI[2][rl] * MEMD;
        const float* g3 = g_G + sI[3][rl] * MEMD;
        float w0 = sWt[0][rl], w1 = sWt[1][rl], w2 = sWt[2][rl], w3 = sWt[3][rl];
#pragma unroll
        for (int cc = 0; cc < 8; cc++) {
            int c = (cc << 5) + lane;
            float a = w0 * __ldg(g0 + c) + w1 * __ldg(g1 + c)
                    + w2 * __ldg(g2 + c) + w3 * __ldg(g3 + c);
            sOut[c * 33 + rl] = a;
        }
    }
    __syncthreads();

    for (int i = tid; i < 256 * 32; i += 256) {
        int c = i >> 5, rl = i & 31;
        int r = rbase + rl;
        if (r < n) out[(long long)c * n + r] = sOut[c * 33 + rl];
    }
}

// ---------------- launch -----------------------------------------------------
extern "C" void kernel_launch(void* const* d_in, const int* in_sizes, int n_in,
                              void* d_out, int out_size) {
    const float* features = (const float*)d_in[0];
    const void*  proj     = d_in[1];
    const void*  mask     = d_in[2];
    const float* Wl       = (const float*)d_in[3];
    const float* bl       = (const float*)d_in[4];
    float* out = (float*)d_out;

    int n = in_sizes[1];                       // 250000 map cells
    long long memElems = (long long)MEMD * n;  // 64,000,000

    float*         maskout_f = nullptr;
    unsigned char* maskout_b = nullptr;
    if ((long long)out_size >= memElems + n) {
        maskout_f = out + memElems;            // float mask appended
    } else if ((long long)out_size > memElems) {
        maskout_b = (unsigned char*)(out + memElems);  // byte-packed bool mask
    }

    k_init<<<1, 1>>>((const int*)proj, n, (const unsigned*)mask);
    k_max<<<512, 256>>>(proj, n);
    k_count<<<NBLK, 256>>>(mask);
    k_scan<<<1, 1024>>>();
    k_prefix<<<NBLK, 256>>>(mask);
    k_gemmG<<<dim3(SRC_PIX / 128, MEMD / 64), 256>>>(features, Wl, bl);
    k_main<<<(n + 31) / 32, 256>>>(proj, out, maskout_f, maskout_b, n);
}

// round 3
// speedup vs baseline: 1.7466x; 1.7466x over previous
#include <cuda_runtime.h>
#include <cuda_fp16.h>

#define HW        (1024*2048)
#define NBLK      1024
#define BPIX      2048
#define SRC_PIX   (128*256)
#define MEMD      256
#define EGO_W     2048

// ---------------- scratch (device globals; allocation-free at runtime) -----
__device__ long long g_thr;
__device__ int       g_is64;    // proj_indices element size flag (1 = int64)
__device__ int       g_msize;   // mask element size in bytes: 1, 4, or 8
__device__ int       g_blkcnt[NBLK];
__device__ int       g_blkoff[NBLK + 1];
__device__ int       g_Pos[HW];                   // positions LUT: slot j -> pixel
__device__ __half    g_Gh[SRC_PIX * MEMD];        // projected source features (+bias), fp16

// ---------------- helpers ---------------------------------------------------
__device__ __forceinline__ int warp_incl_scan(int v) {
    int lane = threadIdx.x & 31;
#pragma unroll
    for (int o = 1; o < 32; o <<= 1) {
        int t = __shfl_up_sync(0xffffffffu, v, o);
        if (lane >= o) v += t;
    }
    return v;
}

// Load 8 consecutive mask pixels starting at pixel index `base` (multiple of 8),
// honoring the detected element size. Returns bits and their sum.
__device__ __forceinline__ int load8bits(const void* mask, size_t base, int msize,
                                         int bits[8]) {
    if (msize == 1) {
        uint2 v = *(const uint2*)((const unsigned char*)mask + base);
#pragma unroll
        for (int i = 0; i < 4; i++) bits[i]     = ((v.x >> (8 * i)) & 0xff) != 0;
#pragma unroll
        for (int i = 0; i < 4; i++) bits[4 + i] = ((v.y >> (8 * i)) & 0xff) != 0;
    } else if (msize == 4) {
        const uint4* p = (const uint4*)((const unsigned*)mask + base);
        uint4 a = p[0], b = p[1];
        bits[0] = a.x != 0; bits[1] = a.y != 0; bits[2] = a.z != 0; bits[3] = a.w != 0;
        bits[4] = b.x != 0; bits[5] = b.y != 0; bits[6] = b.z != 0; bits[7] = b.w != 0;
    } else {
        const uint4* p = (const uint4*)((const unsigned long long*)mask + base);
        uint4 a = p[0], b = p[1], c = p[2], d = p[3];
        bits[0] = (a.x | a.y) != 0; bits[1] = (a.z | a.w) != 0;
        bits[2] = (b.x | b.y) != 0; bits[3] = (b.z | b.w) != 0;
        bits[4] = (c.x | c.y) != 0; bits[5] = (c.z | c.w) != 0;
        bits[6] = (d.x | d.y) != 0; bits[7] = (d.z | d.w) != 0;
    }
    int s = 0;
#pragma unroll
    for (int i = 0; i < 8; i++) s += bits[i];
    return s;
}

// ---------------- K0: init + dtype detection (proj + mask), parallel --------
__global__ void k_init(const int* __restrict__ p32, int n,
                       const unsigned* __restrict__ mw) {
    __shared__ int sAllF, sAllI, sOddZ, sIs64;
    int t = threadIdx.x;
    if (t == 0) {
        sAllF = 1; sAllI = 1; sOddZ = 1; sIs64 = 1;
        g_thr = 0x8000000000000000LL;
    }
    __syncthreads();

    // proj_indices: int64 (odd words all 0/-1) vs int32 (odd words random)
    if (t < 256 && 2 * t + 1 < n) {
        int hi = p32[2 * t + 1];
        if (hi != 0 && hi != -1) sIs64 = 0;
    }
    // mask dtype probe: first 1024 32-bit words
    for (int k = t; k < 1024; k += blockDim.x) {
        unsigned v = mw[k];
        if (v != 0u && v != 0x3F800000u) sAllF = 0;
        if (v > 1u) sAllI = 0;
        if ((k & 1) && v != 0u) sOddZ = 0;
    }
    __syncthreads();
    if (t == 0) {
        g_is64 = sIs64;
        int msize;
        if (sAllI)      msize = sOddZ ? 8 : 4;
        else if (sAllF) msize = 4;
        else            msize = 1;
        g_msize = msize;
    }
}

// ---------------- K1: max(proj_indices) -> g_thr -----------------------------
__global__ void k_max(const void* __restrict__ proj, int n) {
    int is64 = g_is64;
    long long m = 0x8000000000000000LL;
    int stride = gridDim.x * blockDim.x;
    for (int i = blockIdx.x * blockDim.x + threadIdx.x; i < n; i += stride) {
        long long v = is64 ? ((const long long*)proj)[i]
                           : (long long)((const int*)proj)[i];
        m = v > m ? v : m;
    }
#pragma unroll
    for (int o = 16; o; o >>= 1) {
        long long t = __shfl_down_sync(0xffffffffu, m, o);
        m = t > m ? t : m;
    }
    if ((threadIdx.x & 31) == 0) atomicMax(&g_thr, m);
}

// ---------------- K2: per-block inlier counts -------------------------------
__global__ void __launch_bounds__(256) k_count(const void* __restrict__ mask) {
    int t = threadIdx.x;
    int msize = g_msize;
    size_t base = (size_t)blockIdx.x * BPIX + (size_t)t * 8;
    int bits[8];
    int c = load8bits(mask, base, msize, bits);
#pragma unroll
    for (int o = 16; o; o >>= 1) c += __shfl_down_sync(0xffffffffu, c, o);
    __shared__ int ws[8];
    if ((t & 31) == 0) ws[t >> 5] = c;
    __syncthreads();
    if (t == 0) {
        int s = 0;
#pragma unroll
        for (int i = 0; i < 8; i++) s += ws[i];
        g_blkcnt[blockIdx.x] = s;
    }
}

// ---------------- K3: scan block counts (single block) ----------------------
__global__ void __launch_bounds__(1024) k_scan() {
    int t = threadIdx.x;
    int v = g_blkcnt[t];
    int incl = warp_incl_scan(v);
    __shared__ int ws[32];
    if ((t & 31) == 31) ws[t >> 5] = incl;
    __syncthreads();
    if (t < 32) ws[t] = warp_incl_scan(ws[t]);
    __syncthreads();
    if (t >= 32) incl += ws[(t >> 5) - 1];
    g_blkoff[t] = incl - v;               // exclusive offset
    if (t == 1023) g_blkoff[NBLK] = incl; // total inliers
}

// ---------------- K4: prefix + scatter positions LUT ------------------------
// pos[rank(p)] = p, inliers (rank = #inliers before p) first, then outliers.
__global__ void __launch_bounds__(256) k_scatter(const void* __restrict__ mask) {
    int t = threadIdx.x, b = blockIdx.x;
    int msize = g_msize;
    size_t base = (size_t)b * BPIX + (size_t)t * 8;
    int bits[8];
    int s = load8bits(mask, base, msize, bits);

    int incl = warp_incl_scan(s);
    __shared__ int ws[8];
    int w = t >> 5;
    if ((t & 31) == 31) ws[w] = incl;
    __syncthreads();
    if (t == 0) {
        int acc = 0;
#pragma unroll
        for (int i = 0; i < 8; i++) { int tmp = ws[i]; ws[i] = acc; acc += tmp; }
    }
    __syncthreads();
    int run = g_blkoff[b] + (incl - s) + ws[w];   // inliers strictly before my pixels
    int nin = g_blkoff[NBLK];
    int p0 = (int)base;
#pragma unroll
    for (int i = 0; i < 8; i++) {
        int p = p0 + i;
        if (bits[i]) { g_Pos[run] = p; run++; }
        else         { g_Pos[nin + p - run] = p; }
    }
}

// ---------------- K5: project source grid through W (+bias), fp16 out -------
// G[p][n] = sum_c feat[c][p] * W[n][c] + b[n]    (p over 128x256 source pixels)
__global__ void __launch_bounds__(256) k_gemmG(const float* __restrict__ feat,
                                               const float* __restrict__ Wl,
                                               const float* __restrict__ bl) {
    __shared__ float As[64][128];   // [k][px]
    __shared__ float Ws[64][64];    // [n_local][k]
    int pxb = blockIdx.x * 128;
    int nb  = blockIdx.y * 64;
    int t = threadIdx.x;

    for (int i = t; i < 64 * 128; i += 256) {
        int k = i >> 7, px = i & 127;
        As[k][px] = feat[k * SRC_PIX + pxb + px];
    }
    for (int i = t; i < 64 * 16; i += 256) {
        int nl = i >> 4, k4 = i & 15;
        *(float4*)&Ws[nl][k4 * 4] = *(const float4*)&Wl[(nb + nl) * 64 + k4 * 4];
    }
    __syncthreads();

    int lane = t & 31, w = t >> 5;
    int px0 = lane * 4;
    int n0  = w * 8;
    float acc[4][8];
#pragma unroll
    for (int i = 0; i < 4; i++)
#pragma unroll
        for (int j = 0; j < 8; j++) acc[i][j] = 0.0f;

#pragma unroll 8
    for (int k = 0; k < 64; k++) {
        float4 a4 = *(float4*)&As[k][px0];
        float av[4] = {a4.x, a4.y, a4.z, a4.w};
#pragma unroll
        for (int j = 0; j < 8; j++) {
            float bb = Ws[n0 + j][k];
#pragma unroll
            for (int i = 0; i < 4; i++) acc[i][j] = fmaf(av[i], bb, acc[i][j]);
        }
    }

#pragma unroll
    for (int i = 0; i < 4; i++) {
        int row = pxb + px0 + i;
#pragma unroll
        for (int j = 0; j < 8; j += 2) {
            __half2 h = __floats2half2_rn(acc[i][j]     + bl[nb + n0 + j],
                                          acc[i][j + 1] + bl[nb + n0 + j + 1]);
            *(__half2*)&g_Gh[row * MEMD + nb + n0 + j] = h;
        }
    }
}

// ---------------- K6: main fused gather + interpolate + transpose -----------
__global__ void __launch_bounds__(256) k_main(const void* __restrict__ proj,
                                              float* __restrict__ out,
                                              float* __restrict__ maskout_f,
                                              unsigned char* __restrict__ maskout_b,
                                              int n) {
    __shared__ int   sI[4][32];
    __shared__ float sWt[4][32];
    __shared__ float sOut[256 * 33];

    int tid = threadIdx.x;
    int w = tid >> 5, lane = tid & 31;
    int rbase = blockIdx.x * 32;

    // Per-warp setup: lanes 0-3 each resolve one of this warp's 4 rows.
    if (lane < 4) {
        int rl = (w << 2) + lane;
        int r = rbase + rl;
        int i0 = 0, i1 = 0, i2 = 0, i3 = 0;
        float w0 = 0.f, w1 = 0.f, w2 = 0.f, w3 = 0.f;
        if (r < n) {
            long long pj = g_is64 ? ((const long long*)proj)[r]
                                  : (long long)((const int*)proj)[r];
            bool m = pj < g_thr;
            if (maskout_f) maskout_f[r] = m ? 1.0f : 0.0f;
            if (maskout_b) maskout_b[r] = m ? 1 : 0;
            if (m) {
                long long jc = pj < 0 ? 0 : (pj > (long long)(HW - 1) ? (long long)(HW - 1) : pj);
                int p = __ldg(&g_Pos[(int)jc]);        // rank-select via LUT
                int y = p >> 11, x = p & (EGO_W - 1);
                float sy = y * (127.0f / 1023.0f);
                float sx = x * (255.0f / 2047.0f);
                int y0 = (int)sy; if (y0 > 127) y0 = 127;
                int x0 = (int)sx; if (x0 > 255) x0 = 255;
                int y1 = y0 + 1 > 127 ? 127 : y0 + 1;
                int x1 = x0 + 1 > 255 ? 255 : x0 + 1;
                float wy = sy - (float)y0, wx = sx - (float)x0;
                w0 = (1.f - wy) * (1.f - wx);
                w1 = (1.f - wy) * wx;
                w2 = wy * (1.f - wx);
                w3 = wy * wx;
                i0 = y0 * 256 + x0; i1 = y0 * 256 + x1;
                i2 = y1 * 256 + x0; i3 = y1 * 256 + x1;
            }
        }
        sI[0][rl] = i0; sI[1][rl] = i1; sI[2][rl] = i2; sI[3][rl] = i3;
        sWt[0][rl] = w0; sWt[1][rl] = w1; sWt[2][rl] = w2; sWt[3][rl] = w3;
    }
    __syncwarp();

#pragma unroll
    for (int rr = 0; rr < 4; rr++) {
        int rl = (w << 2) + rr;
        const __half2* g0 = (const __half2*)(g_Gh + sI[0][rl] * MEMD);
        const __half2* g1 = (const __half2*)(g_Gh + sI[1][rl] * MEMD);
        const __half2* g2 = (const __half2*)(g_Gh + sI[2][rl] * MEMD);
        const __half2* g3 = (const __half2*)(g_Gh + sI[3][rl] * MEMD);
        float w0 = sWt[0][rl], w1 = sWt[1][rl], w2 = sWt[2][rl], w3 = sWt[3][rl];
#pragma unroll
        for (int cc = 0; cc < 4; cc++) {
            int c2 = (cc << 5) + lane;                 // half2 index: channels 2c2, 2c2+1
            float2 a0 = __half22float2(__ldg(g0 + c2));
            float2 a1 = __half22float2(__ldg(g1 + c2));
            float2 a2 = __half22float2(__ldg(g2 + c2));
            float2 a3 = __half22float2(__ldg(g3 + c2));
            float rlo = w0 * a0.x + w1 * a1.x + w2 * a2.x + w3 * a3.x;
            float rhi = w0 * a0.y + w1 * a1.y + w2 * a2.y + w3 * a3.y;
            sOut[(2 * c2)     * 33 + rl] = rlo;
            sOut[(2 * c2 + 1) * 33 + rl] = rhi;
        }
    }
    __syncthreads();

    for (int i = tid; i < 256 * 32; i += 256) {
        int c = i >> 5, rl = i & 31;
        int r = rbase + rl;
        if (r < n) out[(long long)c * n + r] = sOut[c * 33 + rl];
    }
}

// ---------------- launch -----------------------------------------------------
extern "C" void kernel_launch(void* const* d_in, const int* in_sizes, int n_in,
                              void* d_out, int out_size) {
    const float* features = (const float*)d_in[0];
    const void*  proj     = d_in[1];
    const void*  mask     = d_in[2];
    const float* Wl       = (const float*)d_in[3];
    const float* bl       = (const float*)d_in[4];
    float* out = (float*)d_out;

    int n = in_sizes[1];                       // 250000 map cells
    long long memElems = (long long)MEMD * n;  // 64,000,000

    float*         maskout_f = nullptr;
    unsigned char* maskout_b = nullptr;
    if ((long long)out_size >= memElems + n) {
        maskout_f = out + memElems;            // float mask appended
    } else if ((long long)out_size > memElems) {
        maskout_b = (unsigned char*)(out + memElems);  // byte-packed bool mask
    }

    // Fork a side stream for the independent GEMM (graph-capturable fork/join).
    static cudaStream_t s2 = nullptr;
    static cudaEvent_t evRoot = nullptr, evG = nullptr;
    if (!s2) {
        cudaStreamCreateWithFlags(&s2, cudaStreamNonBlocking);
        cudaEventCreateWithFlags(&evRoot, cudaEventDisableTiming);
        cudaEventCreateWithFlags(&evG, cudaEventDisableTiming);
    }

    cudaEventRecord(evRoot, 0);
    cudaStreamWaitEvent(s2, evRoot, 0);
    k_gemmG<<<dim3(SRC_PIX / 128, MEMD / 64), 256, 0, s2>>>(features, Wl, bl);
    cudaEventRecord(evG, s2);

    k_init<<<1, 512>>>((const int*)proj, n, (const unsigned*)mask);
    k_max<<<256, 256>>>(proj, n);
    k_count<<<NBLK, 256>>>(mask);
    k_scan<<<1, 1024>>>();
    k_scatter<<<NBLK, 256>>>(mask);

    cudaStreamWaitEvent(0, evG, 0);
    k_main<<<(n + 31) / 32, 256>>>(proj, out, maskout_f, maskout_b, n);
}

// round 4
// speedup vs baseline: 1.8552x; 1.0622x over previous
#include <cuda_runtime.h>
#include <cuda_fp16.h>

#define HW        (1024*2048)
#define NBLK      1024
#define BPIX      2048
#define SRC_PIX   (128*256)
#define MEMD      256
#define EGO_W     2048

#define FLAG_A    (1ull << 33)
#define FLAG_P    (1ull << 34)
#define VAL_MASK  0xFFFFFFFFull

// ---------------- scratch (device globals; allocation-free at runtime) -----
__device__ long long          g_thr;
__device__ int                g_is64;    // proj_indices element size flag (1 = int64)
__device__ int                g_msize;   // mask element size in bytes: 1, 4, or 8
__device__ int                g_nin;     // total inlier count
__device__ unsigned long long g_state[NBLK];    // decoupled-lookback states
__device__ int                g_Pos[2 * HW];    // [0,HW): inlier slots; [HW,2HW): outlier slots
__device__ __half             g_Gh[SRC_PIX * MEMD]; // projected source features (+bias), fp16

// ---------------- helpers ---------------------------------------------------
__device__ __forceinline__ int warp_incl_scan(int v) {
    int lane = threadIdx.x & 31;
#pragma unroll
    for (int o = 1; o < 32; o <<= 1) {
        int t = __shfl_up_sync(0xffffffffu, v, o);
        if (lane >= o) v += t;
    }
    return v;
}

// Load 8 consecutive mask pixels starting at pixel index `base` (multiple of 8),
// honoring the detected element size. Returns bits and their sum.
__device__ __forceinline__ int load8bits(const void* mask, size_t base, int msize,
                                         int bits[8]) {
    if (msize == 1) {
        uint2 v = *(const uint2*)((const unsigned char*)mask + base);
#pragma unroll
        for (int i = 0; i < 4; i++) bits[i]     = ((v.x >> (8 * i)) & 0xff) != 0;
#pragma unroll
        for (int i = 0; i < 4; i++) bits[4 + i] = ((v.y >> (8 * i)) & 0xff) != 0;
    } else if (msize == 4) {
        const uint4* p = (const uint4*)((const unsigned*)mask + base);
        uint4 a = p[0], b = p[1];
        bits[0] = a.x != 0; bits[1] = a.y != 0; bits[2] = a.z != 0; bits[3] = a.w != 0;
        bits[4] = b.x != 0; bits[5] = b.y != 0; bits[6] = b.z != 0; bits[7] = b.w != 0;
    } else {
        const uint4* p = (const uint4*)((const unsigned long long*)mask + base);
        uint4 a = p[0], b = p[1], c = p[2], d = p[3];
        bits[0] = (a.x | a.y) != 0; bits[1] = (a.z | a.w) != 0;
        bits[2] = (b.x | b.y) != 0; bits[3] = (b.z | b.w) != 0;
        bits[4] = (c.x | c.y) != 0; bits[5] = (c.z | c.w) != 0;
        bits[6] = (d.x | d.y) != 0; bits[7] = (d.z | d.w) != 0;
    }
    int s = 0;
#pragma unroll
    for (int i = 0; i < 8; i++) s += bits[i];
    return s;
}

// ---------------- K0: init + dtype detection + state reset -------------------
__global__ void k_init(const int* __restrict__ p32, int n,
                       const unsigned* __restrict__ mw) {
    __shared__ int sAllF, sAllI, sOddZ, sIs64;
    int t = threadIdx.x;
    if (t == 0) {
        sAllF = 1; sAllI = 1; sOddZ = 1; sIs64 = 1;
        g_thr = 0x8000000000000000LL;
    }
    __syncthreads();

    // reset lookback states for this launch
    for (int k = t; k < NBLK; k += blockDim.x) g_state[k] = 0ull;

    // proj_indices: int64 (odd words all 0/-1) vs int32 (odd words random)
    if (t < 256 && 2 * t + 1 < n) {
        int hi = p32[2 * t + 1];
        if (hi != 0 && hi != -1) sIs64 = 0;
    }
    // mask dtype probe: first 1024 32-bit words
    for (int k = t; k < 1024; k += blockDim.x) {
        unsigned v = mw[k];
        if (v != 0u && v != 0x3F800000u) sAllF = 0;
        if (v > 1u) sAllI = 0;
        if ((k & 1) && v != 0u) sOddZ = 0;
    }
    __syncthreads();
    if (t == 0) {
        g_is64 = sIs64;
        int msize;
        if (sAllI)      msize = sOddZ ? 8 : 4;
        else if (sAllF) msize = 4;
        else            msize = 1;
        g_msize = msize;
    }
}

// ---------------- K1: max(proj_indices) -> g_thr -----------------------------
__global__ void k_max(const void* __restrict__ proj, int n) {
    int is64 = g_is64;
    long long m = 0x8000000000000000LL;
    int stride = gridDim.x * blockDim.x;
    for (int i = blockIdx.x * blockDim.x + threadIdx.x; i < n; i += stride) {
        long long v = is64 ? ((const long long*)proj)[i]
                           : (long long)((const int*)proj)[i];
        m = v > m ? v : m;
    }
#pragma unroll
    for (int o = 16; o; o >>= 1) {
        long long t = __shfl_down_sync(0xffffffffu, m, o);
        m = t > m ? t : m;
    }
    if ((threadIdx.x & 31) == 0) atomicMax(&g_thr, m);
}

// ---------------- K2: single-pass decoupled-lookback scan + scatter ---------
// pos[rank(p)] = p for inliers; pos[HW + (p - rank(p))] = p for outliers.
__global__ void __launch_bounds__(256) k_scatter_lb(const void* __restrict__ mask) {
    __shared__ int ws[8];
    __shared__ int sExc;

    int t = threadIdx.x, b = blockIdx.x;
    int msize = g_msize;
    size_t base = (size_t)b * BPIX + (size_t)t * 8;
    int bits[8];
    int s = load8bits(mask, base, msize, bits);

    int incl = warp_incl_scan(s);
    int w = t >> 5;
    if ((t & 31) == 31) ws[w] = incl;
    __syncthreads();

    if (t < 32) {
        // exclusive scan of the 8 warp sums + block aggregate (lanes 8..31 carry 0)
        int wsv = (t < 8) ? ws[t] : 0;
        int wincl = warp_incl_scan(wsv);
        int agg = __shfl_sync(0xffffffffu, wincl, 7);
        if (t < 8) ws[t] = wincl - wsv;

        // publish aggregate (block 0 publishes final prefix directly)
        if (t == 0) {
            unsigned long long st = (unsigned long long)agg |
                                    ((b == 0) ? FLAG_P : FLAG_A);
            atomicExch(&g_state[b], st);
        }

        // warp-parallel lookback
        int exc = 0;
        if (b > 0) {
            int j = b - 1;
            while (true) {
                int idx = j - t;
                unsigned long long v = (idx >= 0)
                    ? atomicAdd(&g_state[idx], 0ull)
                    : FLAG_P;                         // virtual prefix 0 below block 0
                bool isP = (v & FLAG_P) != 0;
                bool notR = (v & (FLAG_P | FLAG_A)) == 0;
                unsigned mP  = __ballot_sync(0xffffffffu, isP);
                unsigned mNR = __ballot_sync(0xffffffffu, notR);
                int firstP  = mP  ? (__ffs(mP)  - 1) : 32;
                int firstNR = mNR ? (__ffs(mNR) - 1) : 32;
                if (firstP < firstNR) {
                    int c = (t <= firstP) ? (int)(v & VAL_MASK) : 0;
#pragma unroll
                    for (int o = 16; o; o >>= 1) c += __shfl_xor_sync(0xffffffffu, c, o);
                    exc += c;
                    break;
                } else if (firstNR > 0) {
                    int c = (t < firstNR) ? (int)(v & VAL_MASK) : 0;
#pragma unroll
                    for (int o = 16; o; o >>= 1) c += __shfl_xor_sync(0xffffffffu, c, o);
                    exc += c;
                    j -= firstNR;
                }
                // firstNR == 0: nearest predecessor not ready yet -> spin
            }
        }
        if (t == 0) {
            sExc = exc;
            atomicExch(&g_state[b], (unsigned long long)(exc + agg) | FLAG_P);
            if (b == NBLK - 1) g_nin = exc + agg;
        }
    }
    __syncthreads();

    int run = sExc + (incl - s) + ws[w];   // inliers strictly before my 8 pixels
    int p0 = (int)base;
#pragma unroll
    for (int i = 0; i < 8; i++) {
        int p = p0 + i;
        if (bits[i]) { g_Pos[run] = p; run++; }
        else         { g_Pos[HW + p - run] = p; }
    }
}

// ---------------- K5: project source grid through W (+bias), fp16 out -------
__global__ void __launch_bounds__(256) k_gemmG(const float* __restrict__ feat,
                                               const float* __restrict__ Wl,
                                               const float* __restrict__ bl) {
    __shared__ float As[64][128];   // [k][px]
    __shared__ float Ws[64][64];    // [n_local][k]
    int pxb = blockIdx.x * 128;
    int nb  = blockIdx.y * 64;
    int t = threadIdx.x;

    for (int i = t; i < 64 * 128; i += 256) {
        int k = i >> 7, px = i & 127;
        As[k][px] = feat[k * SRC_PIX + pxb + px];
    }
    for (int i = t; i < 64 * 16; i += 256) {
        int nl = i >> 4, k4 = i & 15;
        *(float4*)&Ws[nl][k4 * 4] = *(const float4*)&Wl[(nb + nl) * 64 + k4 * 4];
    }
    __syncthreads();

    int lane = t & 31, w = t >> 5;
    int px0 = lane * 4;
    int n0  = w * 8;
    float acc[4][8];
#pragma unroll
    for (int i = 0; i < 4; i++)
#pragma unroll
        for (int j = 0; j < 8; j++) acc[i][j] = 0.0f;

#pragma unroll 8
    for (int k = 0; k < 64; k++) {
        float4 a4 = *(float4*)&As[k][px0];
        float av[4] = {a4.x, a4.y, a4.z, a4.w};
#pragma unroll
        for (int j = 0; j < 8; j++) {
            float bb = Ws[n0 + j][k];
#pragma unroll
            for (int i = 0; i < 4; i++) acc[i][j] = fmaf(av[i], bb, acc[i][j]);
        }
    }

#pragma unroll
    for (int i = 0; i < 4; i++) {
        int row = pxb + px0 + i;
#pragma unroll
        for (int j = 0; j < 8; j += 2) {
            __half2 h = __floats2half2_rn(acc[i][j]     + bl[nb + n0 + j],
                                          acc[i][j + 1] + bl[nb + n0 + j + 1]);
            *(__half2*)&g_Gh[row * MEMD + nb + n0 + j] = h;
        }
    }
}

// ---------------- K6: main fused gather + interpolate + transpose -----------
__global__ void __launch_bounds__(256) k_main(const void* __restrict__ proj,
                                              float* __restrict__ out,
                                              float* __restrict__ maskout_f,
                                              unsigned char* __restrict__ maskout_b,
                                              int n) {
    __shared__ int   sI[4][32];
    __shared__ float sWt[4][32];
    __shared__ float sOut[256 * 33];

    int tid = threadIdx.x;
    int w = tid >> 5, lane = tid & 31;
    int rbase = blockIdx.x * 32;

    // Per-warp setup: lanes 0-3 each resolve one of this warp's 4 rows.
    if (lane < 4) {
        int rl = (w << 2) + lane;
        int r = rbase + rl;
        int i0 = 0, i1 = 0, i2 = 0, i3 = 0;
        float w0 = 0.f, w1 = 0.f, w2 = 0.f, w3 = 0.f;
        if (r < n) {
            long long pj = g_is64 ? ((const long long*)proj)[r]
                                  : (long long)((const int*)proj)[r];
            bool m = pj < g_thr;
            if (maskout_f) maskout_f[r] = m ? 1.0f : 0.0f;
            if (maskout_b) maskout_b[r] = m ? 1 : 0;
            if (m) {
                long long jc = pj < 0 ? 0 : (pj > (long long)(HW - 1) ? (long long)(HW - 1) : pj);
                int j = (int)jc;
                int nin = g_nin;
                int idx = (j < nin) ? j : (HW + (j - nin));
                int p = __ldg(&g_Pos[idx]);            // rank-select via split LUT
                int y = p >> 11, x = p & (EGO_W - 1);
                float sy = y * (127.0f / 1023.0f);
                float sx = x * (255.0f / 2047.0f);
                int y0 = (int)sy; if (y0 > 127) y0 = 127;
                int x0 = (int)sx; if (x0 > 255) x0 = 255;
                int y1 = y0 + 1 > 127 ? 127 : y0 + 1;
                int x1 = x0 + 1 > 255 ? 255 : x0 + 1;
                float wy = sy - (float)y0, wx = sx - (float)x0;
                w0 = (1.f - wy) * (1.f - wx);
                w1 = (1.f - wy) * wx;
                w2 = wy * (1.f - wx);
                w3 = wy * wx;
                i0 = y0 * 256 + x0; i1 = y0 * 256 + x1;
                i2 = y1 * 256 + x0; i3 = y1 * 256 + x1;
            }
        }
        sI[0][rl] = i0; sI[1][rl] = i1; sI[2][rl] = i2; sI[3][rl] = i3;
        sWt[0][rl] = w0; sWt[1][rl] = w1; sWt[2][rl] = w2; sWt[3][rl] = w3;
    }
    __syncwarp();

#pragma unroll
    for (int rr = 0; rr < 4; rr++) {
        int rl = (w << 2) + rr;
        const __half2* g0 = (const __half2*)(g_Gh + sI[0][rl] * MEMD);
        const __half2* g1 = (const __half2*)(g_Gh + sI[1][rl] * MEMD);
        const __half2* g2 = (const __half2*)(g_Gh + sI[2][rl] * MEMD);
        const __half2* g3 = (const __half2*)(g_Gh + sI[3][rl] * MEMD);
        float w0 = sWt[0][rl], w1 = sWt[1][rl], w2 = sWt[2][rl], w3 = sWt[3][rl];
#pragma unroll
        for (int cc = 0; cc < 4; cc++) {
            int c2 = (cc << 5) + lane;                 // half2 index: channels 2c2, 2c2+1
            float2 a0 = __half22float2(__ldg(g0 + c2));
            float2 a1 = __half22float2(__ldg(g1 + c2));
            float2 a2 = __half22float2(__ldg(g2 + c2));
            float2 a3 = __half22float2(__ldg(g3 + c2));
            float rlo = w0 * a0.x + w1 * a1.x + w2 * a2.x + w3 * a3.x;
            float rhi = w0 * a0.y + w1 * a1.y + w2 * a2.y + w3 * a3.y;
            sOut[(2 * c2)     * 33 + rl] = rlo;
            sOut[(2 * c2 + 1) * 33 + rl] = rhi;
        }
    }
    __syncthreads();

    // coalesced, evict-streaming stores (keep G resident in L2)
    for (int i = tid; i < 256 * 32; i += 256) {
        int c = i >> 5, rl = i & 31;
        int r = rbase + rl;
        if (r < n) __stcs(&out[(long long)c * n + r], sOut[c * 33 + rl]);
    }
}

// ---------------- launch -----------------------------------------------------
extern "C" void kernel_launch(void* const* d_in, const int* in_sizes, int n_in,
                              void* d_out, int out_size) {
    const float* features = (const float*)d_in[0];
    const void*  proj     = d_in[1];
    const void*  mask     = d_in[2];
    const float* Wl       = (const float*)d_in[3];
    const float* bl       = (const float*)d_in[4];
    float* out = (float*)d_out;

    int n = in_sizes[1];                       // 250000 map cells
    long long memElems = (long long)MEMD * n;  // 64,000,000

    float*         maskout_f = nullptr;
    unsigned char* maskout_b = nullptr;
    if ((long long)out_size >= memElems + n) {
        maskout_f = out + memElems;            // float mask appended
    } else if ((long long)out_size > memElems) {
        maskout_b = (unsigned char*)(out + memElems);  // byte-packed bool mask
    }

    // Fork a side stream for the independent GEMM (graph-capturable fork/join).
    static cudaStream_t s2 = nullptr;
    static cudaEvent_t evRoot = nullptr, evG = nullptr;
    if (!s2) {
        cudaStreamCreateWithFlags(&s2, cudaStreamNonBlocking);
        cudaEventCreateWithFlags(&evRoot, cudaEventDisableTiming);
        cudaEventCreateWithFlags(&evG, cudaEventDisableTiming);
    }

    cudaEventRecord(evRoot, 0);
    cudaStreamWaitEvent(s2, evRoot, 0);
    k_gemmG<<<dim3(SRC_PIX / 128, MEMD / 64), 256, 0, s2>>>(features, Wl, bl);
    cudaEventRecord(evG, s2);

    k_init<<<1, 512>>>((const int*)proj, n, (const unsigned*)mask);
    k_scatter_lb<<<NBLK, 256>>>(mask);
    k_max<<<256, 256>>>(proj, n);

    cudaStreamWaitEvent(0, evG, 0);
    k_main<<<(n + 31) / 32, 256>>>(proj, out, maskout_f, maskout_b, n);
}